// round 8
// baseline (speedup 1.0000x reference)
#include <cuda_runtime.h>
#include <cuda_bf16.h>
#include <cstdint>
#include <math.h>

#define H 256
#define BM 64
#define NSEG 512
#define AS 528           // A row stride in bytes (264 bf16, padded)

typedef unsigned long long u64;
typedef unsigned int       u32;

// -------- device scratch (no allocations allowed) --------
__device__ int g_counts[NSEG];
__device__ int g_is64;
// W packed in per-lane b-fragment layout:
// [gemm(2)][mat hi/lo(2)][kchunk(4)] blocks of 8192 u32 = [ks(4)][nt(32)][lane(32)][reg(2)]
__device__ __align__(16) u32 g_Wb[131072];

// -------- SMEM layout (bytes) --------
#define OFF_AHI   0                    // [64][264] bf16 = 33792
#define OFF_ALO   33792                // 33792
#define OFF_BSEG  67584                // 64 ints = 256
#define OFF_BIAS  67840                // b1[256], b2[256] fp32 = 2048
#define SMEM_TOTAL 69888
// g tile (final): fp32 [64][264] overlays AHI/ALO (written after an extra sync)

// -------- PTX helpers (legal on plain sm_103 target) --------
__device__ __forceinline__ void ldm4(u32* r, u32 addr) {
    asm volatile("ldmatrix.sync.aligned.m8n8.x4.shared.b16 {%0,%1,%2,%3},[%4];"
        : "=r"(r[0]), "=r"(r[1]), "=r"(r[2]), "=r"(r[3]) : "r"(addr));
}
__device__ __forceinline__ void mma16816(float* d, const u32* a, const u32* b) {
    asm volatile(
        "mma.sync.aligned.m16n8k16.row.col.f32.bf16.bf16.f32 "
        "{%0,%1,%2,%3},{%4,%5,%6,%7},{%8,%9},{%0,%1,%2,%3};"
        : "+f"(d[0]), "+f"(d[1]), "+f"(d[2]), "+f"(d[3])
        : "r"(a[0]), "r"(a[1]), "r"(a[2]), "r"(a[3]), "r"(b[0]), "r"(b[1]));
}

// ---------------------------------------------------------------------------
// Kernel 1: zero output + counts, detect batch dtype (int64 vs int32).
// ---------------------------------------------------------------------------
__global__ void zero_kernel(float* out, int out_size, const void* batch, int N) {
    int i = blockIdx.x * blockDim.x + threadIdx.x;
    if (i < out_size) out[i] = 0.0f;
    if (i < NSEG) g_counts[i] = 0;
    if (i == 0) {
        const int* bw = (const int*)batch;
        int o = ((N - 1) & 1) ? (N - 1) : (N - 2);
        int orv = 0;
        if (o >= 4) orv = bw[o] | bw[o - 2] | bw[o - 4];
        else if (o >= 0) orv = bw[o];
        g_is64 = (orv == 0) ? 1 : 0;
    }
}

// ---------------------------------------------------------------------------
// Kernel 2: split W1/W2 fp32 -> bf16 hi/lo, packed in mma b-fragment layout.
// ---------------------------------------------------------------------------
__global__ void wprep_kernel(const float* __restrict__ W1,
                             const float* __restrict__ W2) {
    int id = blockIdx.x * 256 + threadIdx.x;     // 131072 total
    int gemm = id >> 16, rem = id & 65535;
    int n = rem >> 8, k = rem & 255;
    float w = (gemm ? W2 : W1)[n * H + k];
    __nv_bfloat16 hi = __float2bfloat16(w);
    __nv_bfloat16 lo = __float2bfloat16(w - __bfloat162float(hi));
    int chunk = k >> 6, ks = (k >> 4) & 3, kk = k & 15;
    int nt = n >> 3, nn = n & 7;
    int lane = nn * 4 + ((kk & 7) >> 1);
    int reg  = kk >> 3;
    int half = kk & 1;
    u32 base = (u32)(((gemm * 2 + 0) * 4 + chunk) * 8192
                     + ((ks * 32 + nt) * 32 + lane) * 2 + reg);
    __nv_bfloat16* wb = (__nv_bfloat16*)g_Wb;
    wb[(size_t)base * 2 + half] = hi;                       // mat 0 (hi)
    wb[((size_t)base + 32768) * 2 + half] = lo;             // mat 1 (lo)
}

// ---------------------------------------------------------------------------
// Kernel 3: fused  relu(xW1^T+b1) -> sigmoid(hW2^T+b2) gate -> segment reduce.
// bf16 HMMA, 3-term hi/lo compensation. Warp grid 2x4: warp (wr,wc) owns
// rows wr*32..+31 (mt=2) and cols wc*64..+63 (nt=8). Halves LDSM traffic vs
// all-rows-per-warp. B fragments from global (prepacked), double-buffered
// per half-k-step (4 nt at a time) to keep B registers at 32.
// ---------------------------------------------------------------------------
extern "C" __global__ void __launch_bounds__(256, 2)
fused_kernel(const float* __restrict__ x, const void* __restrict__ batch,
             const float* __restrict__ b1, const float* __restrict__ b2,
             float* __restrict__ out, int N)
{
    extern __shared__ char smem[];
    const u32 sb = (u32)__cvta_generic_to_shared(smem);
    const int tid  = threadIdx.x;
    const int w    = tid >> 5;
    const int lane = tid & 31;
    const int wr   = w >> 2;            // 0..1: row group (32 rows)
    const int wc   = w & 3;             // 0..3: col group (64 cols)
    const int row0 = blockIdx.x * BM;
    float* sb1 = (float*)(smem + OFF_BIAS);
    float* sb2 = sb1 + H;
    int* bseg = (int*)(smem + OFF_BSEG);

    // ---- bias + segment ids ----
    sb1[tid] = b1[tid];
    sb2[tid] = b2[tid];
    if (tid < BM) {
        int r = row0 + tid;
        int s = -1;
        if (r < N) {
            if (g_is64) s = (int)((const long long*)batch)[r];
            else        s = ((const int*)batch)[r];
        }
        bseg[tid] = s;
    }

    // ---- load x tile fp32 -> bf16 hi/lo into AHI/ALO ([64][264] padded) ----
    {
        const float4* xg = (const float4*)x;
        #pragma unroll
        for (int it = 0; it < 16; ++it) {
            int f = tid + it * 256;            // 4096 float4s
            int r = f >> 6, k4 = f & 63;
            float4 v = make_float4(0.f, 0.f, 0.f, 0.f);
            if (row0 + r < N) v = xg[(size_t)(row0 + r) * (H / 4) + k4];
            __nv_bfloat162 h01 = __floats2bfloat162_rn(v.x, v.y);
            __nv_bfloat162 h23 = __floats2bfloat162_rn(v.z, v.w);
            float2 f01 = __bfloat1622float2(h01);
            float2 f23 = __bfloat1622float2(h23);
            __nv_bfloat162 l01 = __floats2bfloat162_rn(v.x - f01.x, v.y - f01.y);
            __nv_bfloat162 l23 = __floats2bfloat162_rn(v.z - f23.x, v.w - f23.y);
            char* pa = smem + OFF_AHI + r * AS + k4 * 8;
            char* pl = smem + OFF_ALO + r * AS + k4 * 8;
            *(__nv_bfloat162*)pa = h01;  *(__nv_bfloat162*)(pa + 4) = h23;
            *(__nv_bfloat162*)pl = l01;  *(__nv_bfloat162*)(pl + 4) = l23;
        }
    }
    __syncthreads();   // x tile visible to all warps

    float acc[2][8][4];
    #pragma unroll
    for (int i = 0; i < 2; ++i)
        #pragma unroll
        for (int j = 0; j < 8; ++j)
            #pragma unroll
            for (int q = 0; q < 4; ++q) acc[i][j][q] = 0.f;

    // ---- 2 GEMMs, K=256 = 16 k16-steps = 32 half-steps each ----
    #pragma unroll 1
    for (int g = 0; g < 2; ++g) {
        const u32* bh_base = g_Wb + g * 65536;            // hi blocks
        const u32* bl_base = bh_base + 32768;             // lo blocks
        const u32 lwo = (u32)(wc * 256 + lane) * 2;       // nt = wc*8 base

        uint2 bh[2][4], bl[2][4];
        // preload half 0 (ks=0, jj=0..3)
        #pragma unroll
        for (int jl = 0; jl < 4; ++jl) {
            u32 o = lwo + jl * 64;
            bh[0][jl] = *(const uint2*)(bh_base + o);
            bl[0][jl] = *(const uint2*)(bl_base + o);
        }

        u32 ah[2][4], al[2][4];
        #pragma unroll 2
        for (int hh = 0; hh < 32; ++hh) {
            const int cur = hh & 1, nxt = cur ^ 1;
            const int ks = hh >> 1, h = hh & 1;
            // prefetch next half-step's B fragments (hidden under MMAs)
            if (hh < 31) {
                int h1 = hh + 1;
                int ks1 = h1 >> 1, jb = (h1 & 1) * 4;
                u32 ob = (u32)(ks1 >> 2) * 8192 + (u32)(ks1 & 3) * 2048
                       + (u32)jb * 64 + lwo;
                #pragma unroll
                for (int jl = 0; jl < 4; ++jl) {
                    bh[nxt][jl] = *(const uint2*)(bh_base + ob + jl * 64);
                    bl[nxt][jl] = *(const uint2*)(bl_base + ob + jl * 64);
                }
            }
            // A fragments once per k16-step (reused by both halves)
            if (h == 0) {
                const u32 aoff = (lane & 15) * AS + (ks * 16 + ((lane >> 4) << 3)) * 2
                               + wr * 32 * AS;
                #pragma unroll
                for (int mt = 0; mt < 2; ++mt) {
                    ldm4(ah[mt], sb + OFF_AHI + mt * 16 * AS + aoff);
                    ldm4(al[mt], sb + OFF_ALO + mt * 16 * AS + aoff);
                }
            }
            // 24 MMAs: 2 mt x 4 nt x 3 terms (acc index = h*4+jl)
            #pragma unroll
            for (int mt = 0; mt < 2; ++mt)
                #pragma unroll
                for (int jl = 0; jl < 4; ++jl)
                    mma16816(acc[mt][h * 4 + jl], ah[mt], (const u32*)&bh[cur][jl]);
            #pragma unroll
            for (int mt = 0; mt < 2; ++mt)
                #pragma unroll
                for (int jl = 0; jl < 4; ++jl)
                    mma16816(acc[mt][h * 4 + jl], al[mt], (const u32*)&bh[cur][jl]);
            #pragma unroll
            for (int mt = 0; mt < 2; ++mt)
                #pragma unroll
                for (int jl = 0; jl < 4; ++jl)
                    mma16816(acc[mt][h * 4 + jl], ah[mt], (const u32*)&bl[cur][jl]);
        }

        // ---- GEMM boundary: h = relu(D1+b1) -> bf16 hi/lo back into A ----
        if (g == 0) {
            __syncthreads();   // all warps done READING x before overwrite
            #pragma unroll
            for (int mt = 0; mt < 2; ++mt)
                #pragma unroll
                for (int j = 0; j < 8; ++j) {
                    float* a4 = acc[mt][j];
                    int r  = wr * 32 + mt * 16 + (lane >> 2);
                    int cc = wc * 64 + j * 8 + (lane & 3) * 2;
                    float bx = sb1[cc], by = sb1[cc + 1];
                    float h0 = fmaxf(a4[0] + bx, 0.f), h1 = fmaxf(a4[1] + by, 0.f);
                    float h2 = fmaxf(a4[2] + bx, 0.f), h3 = fmaxf(a4[3] + by, 0.f);
                    __nv_bfloat162 hiA = __floats2bfloat162_rn(h0, h1);
                    __nv_bfloat162 hiB = __floats2bfloat162_rn(h2, h3);
                    float2 fA = __bfloat1622float2(hiA);
                    float2 fB = __bfloat1622float2(hiB);
                    __nv_bfloat162 loA = __floats2bfloat162_rn(h0 - fA.x, h1 - fA.y);
                    __nv_bfloat162 loB = __floats2bfloat162_rn(h2 - fB.x, h3 - fB.y);
                    *(__nv_bfloat162*)(smem + OFF_AHI + r * AS + cc * 2)       = hiA;
                    *(__nv_bfloat162*)(smem + OFF_AHI + (r + 8) * AS + cc * 2) = hiB;
                    *(__nv_bfloat162*)(smem + OFF_ALO + r * AS + cc * 2)       = loA;
                    *(__nv_bfloat162*)(smem + OFF_ALO + (r + 8) * AS + cc * 2) = loB;
                }
            __syncthreads();   // h visible to all warps before GEMM2
            #pragma unroll
            for (int i = 0; i < 2; ++i)
                #pragma unroll
                for (int j = 0; j < 8; ++j)
                    #pragma unroll
                    for (int q = 0; q < 4; ++q) acc[i][j][q] = 0.f;
        }
    }

    // ---- final epilogue: g = h * sigmoid(D2+b2); g overlays A region ----
    float* gt = (float*)smem;   // [64][264] fp32 over AHI+ALO
    {
        float gv[2][8][4];
        #pragma unroll
        for (int mt = 0; mt < 2; ++mt)
            #pragma unroll
            for (int j = 0; j < 8; ++j) {
                float* a4 = acc[mt][j];
                int r  = wr * 32 + mt * 16 + (lane >> 2);
                int cc = wc * 64 + j * 8 + (lane & 3) * 2;
                float bx = sb2[cc], by = sb2[cc + 1];
                float2 hA = __bfloat1622float2(*(__nv_bfloat162*)(smem + OFF_AHI + r * AS + cc * 2));
                float2 lA = __bfloat1622float2(*(__nv_bfloat162*)(smem + OFF_ALO + r * AS + cc * 2));
                float2 hB = __bfloat1622float2(*(__nv_bfloat162*)(smem + OFF_AHI + (r + 8) * AS + cc * 2));
                float2 lB = __bfloat1622float2(*(__nv_bfloat162*)(smem + OFF_ALO + (r + 8) * AS + cc * 2));
                gv[mt][j][0] = (hA.x + lA.x) / (1.f + __expf(-(a4[0] + bx)));
                gv[mt][j][1] = (hA.y + lA.y) / (1.f + __expf(-(a4[1] + by)));
                gv[mt][j][2] = (hB.x + lB.x) / (1.f + __expf(-(a4[2] + bx)));
                gv[mt][j][3] = (hB.y + lB.y) / (1.f + __expf(-(a4[3] + by)));
            }
        __syncthreads();   // everyone done reading h before overwrite
        #pragma unroll
        for (int mt = 0; mt < 2; ++mt)
            #pragma unroll
            for (int j = 0; j < 8; ++j) {
                int r  = wr * 32 + mt * 16 + (lane >> 2);
                int cc = wc * 64 + j * 8 + (lane & 3) * 2;
                *(float2*)&gt[r * 264 + cc]       = make_float2(gv[mt][j][0], gv[mt][j][1]);
                *(float2*)&gt[(r + 8) * 264 + cc] = make_float2(gv[mt][j][2], gv[mt][j][3]);
            }
    }
    __syncthreads();

    // ---- segment reduction: sorted batch -> runs; one thread per column ----
    {
        const int ccol = tid;              // 256 threads = 256 columns
        int cur = bseg[0];
        float rsum = 0.f, rmax = 0.f;
        #pragma unroll 1
        for (int r = 0; r < BM; ++r) {
            int s = bseg[r];
            float g = gt[r * 264 + ccol];
            if (s != cur) {
                if (cur >= 0) {
                    atomicAdd(&out[(size_t)cur * 2 * H + H + ccol], rsum);
                    atomicMax((unsigned int*)&out[(size_t)cur * 2 * H + ccol],
                              __float_as_uint(rmax));   // g >= 0 always
                }
                cur = s; rsum = 0.f; rmax = 0.f;
            }
            if (s >= 0) { rsum += g; rmax = fmaxf(rmax, g); }
        }
        if (cur >= 0) {
            atomicAdd(&out[(size_t)cur * 2 * H + H + ccol], rsum);
            atomicMax((unsigned int*)&out[(size_t)cur * 2 * H + ccol],
                      __float_as_uint(rmax));
        }
        if (tid == 0) {                    // counts: once per run per tile
            int cur2 = bseg[0]; int cnt = 0;
            for (int r = 0; r < BM; ++r) {
                int s = bseg[r];
                if (s != cur2) {
                    if (cur2 >= 0) atomicAdd(&g_counts[cur2], cnt);
                    cur2 = s; cnt = 0;
                }
                if (s >= 0) cnt++;
            }
            if (cur2 >= 0) atomicAdd(&g_counts[cur2], cnt);
        }
    }
}

// ---------------------------------------------------------------------------
// Kernel 4: mean = sum / count (empty segments stay 0)
// ---------------------------------------------------------------------------
__global__ void finalize_kernel(float* out) {
    int i = blockIdx.x * blockDim.x + threadIdx.x;  // NSEG * H
    if (i < NSEG * H) {
        int seg = i >> 8;
        int c   = i & (H - 1);
        int cnt = g_counts[seg];
        float denom = cnt > 0 ? (float)cnt : 1.f;
        out[(size_t)seg * 2 * H + H + c] *= (1.f / denom);
    }
}

extern "C" void kernel_launch(void* const* d_in, const int* in_sizes, int n_in,
                              void* d_out, int out_size) {
    const float* x     = (const float*)d_in[0];
    const void*  batch = d_in[1];
    const float* W1    = (const float*)d_in[2];
    const float* b1    = (const float*)d_in[3];
    const float* W2    = (const float*)d_in[4];
    const float* b2    = (const float*)d_in[5];
    float* out = (float*)d_out;

    int N = in_sizes[0] / H;

    cudaFuncSetAttribute(fused_kernel,
                         cudaFuncAttributeMaxDynamicSharedMemorySize, SMEM_TOTAL);

    zero_kernel<<<(out_size + 255) / 256, 256>>>(out, out_size, batch, N);
    wprep_kernel<<<512, 256>>>(W1, W2);

    int nblk = (N + BM - 1) / BM;
    fused_kernel<<<nblk, 256, SMEM_TOTAL>>>(x, batch, b1, b2, out, N);

    finalize_kernel<<<(NSEG * H + 255) / 256, 256>>>(out);
}

// round 9
// speedup vs baseline: 1.1897x; 1.1897x over previous
#include <cuda_runtime.h>
#include <cuda_fp16.h>
#include <cstdint>
#include <math.h>

#define H 256
#define BM 64
#define NSEG 512
#define AS 528           // A row stride in bytes (264 fp16, padded)

typedef unsigned long long u64;
typedef unsigned int       u32;

// -------- device scratch (no allocations allowed) --------
__device__ int g_counts[NSEG];
__device__ int g_is64;
// W (fp16 hi only) packed in per-lane b-fragment layout:
// [gemm(2)][kchunk(4)] blocks of 8192 u32 = [ks(4)][nt(32)][lane(32)][reg(2)]
__device__ __align__(16) u32 g_Wb[65536];

// -------- SMEM layout (bytes) --------
#define OFF_AHI   0                    // [64][264] fp16 = 33792
#define OFF_ALO   33792                // 33792
#define OFF_BSEG  67584                // 64 ints = 256
#define OFF_BIAS  67840                // b1[256], b2[256] fp32 = 2048
#define SMEM_TOTAL 69888
// g tile (final): fp32 [64][264] overlays AHI/ALO (written after an extra sync)

// -------- PTX helpers (legal on plain sm_103 target) --------
__device__ __forceinline__ void ldm4(u32* r, u32 addr) {
    asm volatile("ldmatrix.sync.aligned.m8n8.x4.shared.b16 {%0,%1,%2,%3},[%4];"
        : "=r"(r[0]), "=r"(r[1]), "=r"(r[2]), "=r"(r[3]) : "r"(addr));
}
__device__ __forceinline__ void mma16816(float* d, const u32* a, const u32* b) {
    asm volatile(
        "mma.sync.aligned.m16n8k16.row.col.f32.f16.f16.f32 "
        "{%0,%1,%2,%3},{%4,%5,%6,%7},{%8,%9},{%0,%1,%2,%3};"
        : "+f"(d[0]), "+f"(d[1]), "+f"(d[2]), "+f"(d[3])
        : "r"(a[0]), "r"(a[1]), "r"(a[2]), "r"(a[3]), "r"(b[0]), "r"(b[1]));
}

// ---------------------------------------------------------------------------
// Kernel 1: zero output + counts, detect batch dtype (int64 vs int32).
// ---------------------------------------------------------------------------
__global__ void zero_kernel(float* out, int out_size, const void* batch, int N) {
    int i = blockIdx.x * blockDim.x + threadIdx.x;
    if (i < out_size) out[i] = 0.0f;
    if (i < NSEG) g_counts[i] = 0;
    if (i == 0) {
        const int* bw = (const int*)batch;
        int o = ((N - 1) & 1) ? (N - 1) : (N - 2);
        int orv = 0;
        if (o >= 4) orv = bw[o] | bw[o - 2] | bw[o - 4];
        else if (o >= 0) orv = bw[o];
        g_is64 = (orv == 0) ? 1 : 0;
    }
}

// ---------------------------------------------------------------------------
// Kernel 2: W1/W2 fp32 -> fp16, packed in mma b-fragment layout (hi only;
// the W residual is dropped — fp16 2-term scheme keeps x exact instead).
// ---------------------------------------------------------------------------
__global__ void wprep_kernel(const float* __restrict__ W1,
                             const float* __restrict__ W2) {
    int id = blockIdx.x * 256 + threadIdx.x;     // 131072 total
    int gemm = id >> 16, rem = id & 65535;
    int n = rem >> 8, k = rem & 255;
    float w = (gemm ? W2 : W1)[n * H + k];
    __half hi = __float2half_rn(w);
    int chunk = k >> 6, ks = (k >> 4) & 3, kk = k & 15;
    int nt = n >> 3, nn = n & 7;
    int lane = nn * 4 + ((kk & 7) >> 1);
    int reg  = kk >> 3;
    int half_i = kk & 1;
    u32 base = (u32)((gemm * 4 + chunk) * 8192
                     + ((ks * 32 + nt) * 32 + lane) * 2 + reg);
    __half* wb = (__half*)g_Wb;
    wb[(size_t)base * 2 + half_i] = hi;
}

// ---------------------------------------------------------------------------
// Kernel 3: fused  relu(xW1^T+b1) -> sigmoid(hW2^T+b2) gate -> segment reduce.
// fp16 HMMA, 2-term: (x_hi + x_lo) x fp16(W) == exact-x times fp16 W.
// Warp grid 2x4 (rows 32*wr, cols 64*wc). B fragments from global
// (prepacked), double-buffered per half-k-step.
// ---------------------------------------------------------------------------
extern "C" __global__ void __launch_bounds__(256, 2)
fused_kernel(const float* __restrict__ x, const void* __restrict__ batch,
             const float* __restrict__ b1, const float* __restrict__ b2,
             float* __restrict__ out, int N)
{
    extern __shared__ char smem[];
    const u32 sb = (u32)__cvta_generic_to_shared(smem);
    const int tid  = threadIdx.x;
    const int w    = tid >> 5;
    const int lane = tid & 31;
    const int wr   = w >> 2;            // 0..1: row group (32 rows)
    const int wc   = w & 3;             // 0..3: col group (64 cols)
    const int row0 = blockIdx.x * BM;
    float* sb1 = (float*)(smem + OFF_BIAS);
    float* sb2 = sb1 + H;
    int* bseg = (int*)(smem + OFF_BSEG);

    // ---- bias + segment ids ----
    sb1[tid] = b1[tid];
    sb2[tid] = b2[tid];
    if (tid < BM) {
        int r = row0 + tid;
        int s = -1;
        if (r < N) {
            if (g_is64) s = (int)((const long long*)batch)[r];
            else        s = ((const int*)batch)[r];
        }
        bseg[tid] = s;
    }

    // ---- load x tile fp32 -> fp16 hi/lo into AHI/ALO ([64][264] padded) ----
    {
        const float4* xg = (const float4*)x;
        #pragma unroll
        for (int it = 0; it < 16; ++it) {
            int f = tid + it * 256;            // 4096 float4s
            int r = f >> 6, k4 = f & 63;
            float4 v = make_float4(0.f, 0.f, 0.f, 0.f);
            if (row0 + r < N) v = xg[(size_t)(row0 + r) * (H / 4) + k4];
            __half2 h01 = __floats2half2_rn(v.x, v.y);
            __half2 h23 = __floats2half2_rn(v.z, v.w);
            float2 f01 = __half22float2(h01);
            float2 f23 = __half22float2(h23);
            __half2 l01 = __floats2half2_rn(v.x - f01.x, v.y - f01.y);
            __half2 l23 = __floats2half2_rn(v.z - f23.x, v.w - f23.y);
            char* pa = smem + OFF_AHI + r * AS + k4 * 8;
            char* pl = smem + OFF_ALO + r * AS + k4 * 8;
            *(__half2*)pa = h01;  *(__half2*)(pa + 4) = h23;
            *(__half2*)pl = l01;  *(__half2*)(pl + 4) = l23;
        }
    }
    __syncthreads();   // x tile visible to all warps

    float acc[2][8][4];
    #pragma unroll
    for (int i = 0; i < 2; ++i)
        #pragma unroll
        for (int j = 0; j < 8; ++j)
            #pragma unroll
            for (int q = 0; q < 4; ++q) acc[i][j][q] = 0.f;

    // ---- 2 GEMMs, K=256 = 16 k16-steps = 32 half-steps each ----
    #pragma unroll 1
    for (int g = 0; g < 2; ++g) {
        const u32* bh_base = g_Wb + g * 32768;            // fp16 W blocks
        const u32 lwo = (u32)(wc * 256 + lane) * 2;       // nt = wc*8 base

        uint2 bh[2][4];
        // preload half 0 (ks=0, jl=0..3)
        #pragma unroll
        for (int jl = 0; jl < 4; ++jl)
            bh[0][jl] = *(const uint2*)(bh_base + lwo + jl * 64);

        u32 ah[2][4], al[2][4];
        #pragma unroll 2
        for (int hh = 0; hh < 32; ++hh) {
            const int cur = hh & 1, nxt = cur ^ 1;
            const int ks = hh >> 1, h = hh & 1;
            // prefetch next half-step's B fragments (hidden under MMAs)
            if (hh < 31) {
                int h1 = hh + 1;
                int ks1 = h1 >> 1, jb = (h1 & 1) * 4;
                u32 ob = (u32)(ks1 >> 2) * 8192 + (u32)(ks1 & 3) * 2048
                       + (u32)jb * 64 + lwo;
                #pragma unroll
                for (int jl = 0; jl < 4; ++jl)
                    bh[nxt][jl] = *(const uint2*)(bh_base + ob + jl * 64);
            }
            // A fragments once per k16-step (reused by both halves)
            if (h == 0) {
                const u32 aoff = (lane & 15) * AS + (ks * 16 + ((lane >> 4) << 3)) * 2
                               + wr * 32 * AS;
                #pragma unroll
                for (int mt = 0; mt < 2; ++mt) {
                    ldm4(ah[mt], sb + OFF_AHI + mt * 16 * AS + aoff);
                    ldm4(al[mt], sb + OFF_ALO + mt * 16 * AS + aoff);
                }
            }
            // 16 MMAs: 2 mt x 4 nt x 2 terms (acc index = h*4+jl)
            #pragma unroll
            for (int mt = 0; mt < 2; ++mt)
                #pragma unroll
                for (int jl = 0; jl < 4; ++jl)
                    mma16816(acc[mt][h * 4 + jl], ah[mt], (const u32*)&bh[cur][jl]);
            #pragma unroll
            for (int mt = 0; mt < 2; ++mt)
                #pragma unroll
                for (int jl = 0; jl < 4; ++jl)
                    mma16816(acc[mt][h * 4 + jl], al[mt], (const u32*)&bh[cur][jl]);
        }

        // ---- GEMM boundary: h = relu(D1+b1) -> fp16 hi/lo back into A ----
        if (g == 0) {
            __syncthreads();   // all warps done READING x before overwrite
            #pragma unroll
            for (int mt = 0; mt < 2; ++mt)
                #pragma unroll
                for (int j = 0; j < 8; ++j) {
                    float* a4 = acc[mt][j];
                    int r  = wr * 32 + mt * 16 + (lane >> 2);
                    int cc = wc * 64 + j * 8 + (lane & 3) * 2;
                    float bx = sb1[cc], by = sb1[cc + 1];
                    float h0 = fmaxf(a4[0] + bx, 0.f), h1 = fmaxf(a4[1] + by, 0.f);
                    float h2 = fmaxf(a4[2] + bx, 0.f), h3 = fmaxf(a4[3] + by, 0.f);
                    __half2 hiA = __floats2half2_rn(h0, h1);
                    __half2 hiB = __floats2half2_rn(h2, h3);
                    float2 fA = __half22float2(hiA);
                    float2 fB = __half22float2(hiB);
                    __half2 loA = __floats2half2_rn(h0 - fA.x, h1 - fA.y);
                    __half2 loB = __floats2half2_rn(h2 - fB.x, h3 - fB.y);
                    *(__half2*)(smem + OFF_AHI + r * AS + cc * 2)       = hiA;
                    *(__half2*)(smem + OFF_AHI + (r + 8) * AS + cc * 2) = hiB;
                    *(__half2*)(smem + OFF_ALO + r * AS + cc * 2)       = loA;
                    *(__half2*)(smem + OFF_ALO + (r + 8) * AS + cc * 2) = loB;
                }
            __syncthreads();   // h visible to all warps before GEMM2
            #pragma unroll
            for (int i = 0; i < 2; ++i)
                #pragma unroll
                for (int j = 0; j < 8; ++j)
                    #pragma unroll
                    for (int q = 0; q < 4; ++q) acc[i][j][q] = 0.f;
        }
    }

    // ---- final epilogue: g = h * sigmoid(D2+b2); g overlays A region ----
    float* gt = (float*)smem;   // [64][264] fp32 over AHI+ALO
    {
        float gv[2][8][4];
        #pragma unroll
        for (int mt = 0; mt < 2; ++mt)
            #pragma unroll
            for (int j = 0; j < 8; ++j) {
                float* a4 = acc[mt][j];
                int r  = wr * 32 + mt * 16 + (lane >> 2);
                int cc = wc * 64 + j * 8 + (lane & 3) * 2;
                float bx = sb2[cc], by = sb2[cc + 1];
                float2 hA = __half22float2(*(__half2*)(smem + OFF_AHI + r * AS + cc * 2));
                float2 lA = __half22float2(*(__half2*)(smem + OFF_ALO + r * AS + cc * 2));
                float2 hB = __half22float2(*(__half2*)(smem + OFF_AHI + (r + 8) * AS + cc * 2));
                float2 lB = __half22float2(*(__half2*)(smem + OFF_ALO + (r + 8) * AS + cc * 2));
                gv[mt][j][0] = (hA.x + lA.x) / (1.f + __expf(-(a4[0] + bx)));
                gv[mt][j][1] = (hA.y + lA.y) / (1.f + __expf(-(a4[1] + by)));
                gv[mt][j][2] = (hB.x + lB.x) / (1.f + __expf(-(a4[2] + bx)));
                gv[mt][j][3] = (hB.y + lB.y) / (1.f + __expf(-(a4[3] + by)));
            }
        __syncthreads();   // everyone done reading h before overwrite
        #pragma unroll
        for (int mt = 0; mt < 2; ++mt)
            #pragma unroll
            for (int j = 0; j < 8; ++j) {
                int r  = wr * 32 + mt * 16 + (lane >> 2);
                int cc = wc * 64 + j * 8 + (lane & 3) * 2;
                *(float2*)&gt[r * 264 + cc]       = make_float2(gv[mt][j][0], gv[mt][j][1]);
                *(float2*)&gt[(r + 8) * 264 + cc] = make_float2(gv[mt][j][2], gv[mt][j][3]);
            }
    }
    __syncthreads();

    // ---- segment reduction: sorted batch -> runs; one thread per column ----
    {
        const int ccol = tid;              // 256 threads = 256 columns
        int cur = bseg[0];
        float rsum = 0.f, rmax = 0.f;
        #pragma unroll 1
        for (int r = 0; r < BM; ++r) {
            int s = bseg[r];
            float g = gt[r * 264 + ccol];
            if (s != cur) {
                if (cur >= 0) {
                    atomicAdd(&out[(size_t)cur * 2 * H + H + ccol], rsum);
                    atomicMax((unsigned int*)&out[(size_t)cur * 2 * H + ccol],
                              __float_as_uint(rmax));   // g >= 0 always
                }
                cur = s; rsum = 0.f; rmax = 0.f;
            }
            if (s >= 0) { rsum += g; rmax = fmaxf(rmax, g); }
        }
        if (cur >= 0) {
            atomicAdd(&out[(size_t)cur * 2 * H + H + ccol], rsum);
            atomicMax((unsigned int*)&out[(size_t)cur * 2 * H + ccol],
                      __float_as_uint(rmax));
        }
        if (tid == 0) {                    // counts: once per run per tile
            int cur2 = bseg[0]; int cnt = 0;
            for (int r = 0; r < BM; ++r) {
                int s = bseg[r];
                if (s != cur2) {
                    if (cur2 >= 0) atomicAdd(&g_counts[cur2], cnt);
                    cur2 = s; cnt = 0;
                }
                if (s >= 0) cnt++;
            }
            if (cur2 >= 0) atomicAdd(&g_counts[cur2], cnt);
        }
    }
}

// ---------------------------------------------------------------------------
// Kernel 4: mean = sum / count (empty segments stay 0)
// ---------------------------------------------------------------------------
__global__ void finalize_kernel(float* out) {
    int i = blockIdx.x * blockDim.x + threadIdx.x;  // NSEG * H
    if (i < NSEG * H) {
        int seg = i >> 8;
        int c   = i & (H - 1);
        int cnt = g_counts[seg];
        float denom = cnt > 0 ? (float)cnt : 1.f;
        out[(size_t)seg * 2 * H + H + c] *= (1.f / denom);
    }
}

extern "C" void kernel_launch(void* const* d_in, const int* in_sizes, int n_in,
                              void* d_out, int out_size) {
    const float* x     = (const float*)d_in[0];
    const void*  batch = d_in[1];
    const float* W1    = (const float*)d_in[2];
    const float* b1    = (const float*)d_in[3];
    const float* W2    = (const float*)d_in[4];
    const float* b2    = (const float*)d_in[5];
    float* out = (float*)d_out;

    int N = in_sizes[0] / H;

    cudaFuncSetAttribute(fused_kernel,
                         cudaFuncAttributeMaxDynamicSharedMemorySize, SMEM_TOTAL);

    zero_kernel<<<(out_size + 255) / 256, 256>>>(out, out_size, batch, N);
    wprep_kernel<<<512, 256>>>(W1, W2);

    int nblk = (N + BM - 1) / BM;
    fused_kernel<<<nblk, 256, SMEM_TOTAL>>>(x, batch, b1, b2, out, N);

    finalize_kernel<<<(NSEG * H + 255) / 256, 256>>>(out);
}

// round 10
// speedup vs baseline: 1.3841x; 1.1634x over previous
#include <cuda_runtime.h>
#include <cuda_fp16.h>
#include <cstdint>
#include <math.h>

#define H 256
#define BM 64
#define NSEG 512
#define AS 528           // A row stride in bytes (264 fp16, padded)

typedef unsigned long long u64;
typedef unsigned int       u32;

// -------- device scratch (no allocations allowed) --------
__device__ int g_counts[NSEG];
__device__ int g_is64;
// W (fp16) packed in per-lane b-fragment layout:
// [gemm(2)][kchunk(4)] blocks of 8192 u32 = [ks(4)][nt(32)][lane(32)][reg(2)]
__device__ __align__(16) u32 g_Wb[65536];

// -------- SMEM layout (bytes) --------
#define OFF_AHI   0                    // [64][264] fp16 = 33792
#define OFF_BSEG  67584                // 64 ints = 256 (gtile fp32 needs 67584)
#define OFF_BIAS  67840                // b1[256], b2[256] fp32 = 2048
#define SMEM_TOTAL 69888
// g tile (final): fp32 [64][264] overlays bytes 0..67583 (A dead by then)

// -------- PTX helpers (legal on plain sm_103 target) --------
__device__ __forceinline__ void ldm4(u32* r, u32 addr) {
    asm volatile("ldmatrix.sync.aligned.m8n8.x4.shared.b16 {%0,%1,%2,%3},[%4];"
        : "=r"(r[0]), "=r"(r[1]), "=r"(r[2]), "=r"(r[3]) : "r"(addr));
}
__device__ __forceinline__ void mma16816(float* d, const u32* a, const u32* b) {
    asm volatile(
        "mma.sync.aligned.m16n8k16.row.col.f32.f16.f16.f32 "
        "{%0,%1,%2,%3},{%4,%5,%6,%7},{%8,%9},{%0,%1,%2,%3};"
        : "+f"(d[0]), "+f"(d[1]), "+f"(d[2]), "+f"(d[3])
        : "r"(a[0]), "r"(a[1]), "r"(a[2]), "r"(a[3]), "r"(b[0]), "r"(b[1]));
}

// ---------------------------------------------------------------------------
// Kernel 1: zero output + counts, detect batch dtype (int64 vs int32).
// ---------------------------------------------------------------------------
__global__ void zero_kernel(float* out, int out_size, const void* batch, int N) {
    int i = blockIdx.x * blockDim.x + threadIdx.x;
    if (i < out_size) out[i] = 0.0f;
    if (i < NSEG) g_counts[i] = 0;
    if (i == 0) {
        const int* bw = (const int*)batch;
        int o = ((N - 1) & 1) ? (N - 1) : (N - 2);
        int orv = 0;
        if (o >= 4) orv = bw[o] | bw[o - 2] | bw[o - 4];
        else if (o >= 0) orv = bw[o];
        g_is64 = (orv == 0) ? 1 : 0;
    }
}

// ---------------------------------------------------------------------------
// Kernel 2: W1/W2 fp32 -> fp16, packed in mma b-fragment layout.
// ---------------------------------------------------------------------------
__global__ void wprep_kernel(const float* __restrict__ W1,
                             const float* __restrict__ W2) {
    int id = blockIdx.x * 256 + threadIdx.x;     // 131072 total
    int gemm = id >> 16, rem = id & 65535;
    int n = rem >> 8, k = rem & 255;
    float w = (gemm ? W2 : W1)[n * H + k];
    __half hi = __float2half_rn(w);
    int chunk = k >> 6, ks = (k >> 4) & 3, kk = k & 15;
    int nt = n >> 3, nn = n & 7;
    int lane = nn * 4 + ((kk & 7) >> 1);
    int reg  = kk >> 3;
    int half_i = kk & 1;
    u32 base = (u32)((gemm * 4 + chunk) * 8192
                     + ((ks * 32 + nt) * 32 + lane) * 2 + reg);
    __half* wb = (__half*)g_Wb;
    wb[(size_t)base * 2 + half_i] = hi;
}

// ---------------------------------------------------------------------------
// Kernel 3: fused  relu(xW1^T+b1) -> sigmoid(hW2^T+b2) gate -> segment reduce.
// Plain fp16 HMMA (1-term: fp16 x, fp16 W — error ~1.5e-4 << 1e-3 threshold).
// Warp grid 2x4 (rows 32*wr, cols 64*wc). B fragments from global
// (prepacked), double-buffered per half-k-step.
// ---------------------------------------------------------------------------
extern "C" __global__ void __launch_bounds__(256, 2)
fused_kernel(const float* __restrict__ x, const void* __restrict__ batch,
             const float* __restrict__ b1, const float* __restrict__ b2,
             float* __restrict__ out, int N)
{
    extern __shared__ char smem[];
    const u32 sb = (u32)__cvta_generic_to_shared(smem);
    const int tid  = threadIdx.x;
    const int w    = tid >> 5;
    const int lane = tid & 31;
    const int wr   = w >> 2;            // 0..1: row group (32 rows)
    const int wc   = w & 3;             // 0..3: col group (64 cols)
    const int row0 = blockIdx.x * BM;
    float* sb1 = (float*)(smem + OFF_BIAS);
    float* sb2 = sb1 + H;
    int* bseg = (int*)(smem + OFF_BSEG);

    // ---- bias + segment ids ----
    sb1[tid] = b1[tid];
    sb2[tid] = b2[tid];
    if (tid < BM) {
        int r = row0 + tid;
        int s = -1;
        if (r < N) {
            if (g_is64) s = (int)((const long long*)batch)[r];
            else        s = ((const int*)batch)[r];
        }
        bseg[tid] = s;
    }

    // ---- load x tile fp32 -> fp16 into AHI ([64][264] padded) ----
    {
        const float4* xg = (const float4*)x;
        #pragma unroll
        for (int it = 0; it < 16; ++it) {
            int f = tid + it * 256;            // 4096 float4s
            int r = f >> 6, k4 = f & 63;
            float4 v = make_float4(0.f, 0.f, 0.f, 0.f);
            if (row0 + r < N) v = xg[(size_t)(row0 + r) * (H / 4) + k4];
            __half2 h01 = __floats2half2_rn(v.x, v.y);
            __half2 h23 = __floats2half2_rn(v.z, v.w);
            char* pa = smem + OFF_AHI + r * AS + k4 * 8;
            *(__half2*)pa = h01;  *(__half2*)(pa + 4) = h23;
        }
    }
    __syncthreads();   // x tile visible to all warps

    float acc[2][8][4];
    #pragma unroll
    for (int i = 0; i < 2; ++i)
        #pragma unroll
        for (int j = 0; j < 8; ++j)
            #pragma unroll
            for (int q = 0; q < 4; ++q) acc[i][j][q] = 0.f;

    // ---- 2 GEMMs, K=256 = 16 k16-steps = 32 half-steps each ----
    #pragma unroll 1
    for (int g = 0; g < 2; ++g) {
        const u32* bh_base = g_Wb + g * 32768;            // fp16 W blocks
        const u32 lwo = (u32)(wc * 256 + lane) * 2;       // nt = wc*8 base

        uint2 bh[2][4];
        // preload half 0 (ks=0, jl=0..3)
        #pragma unroll
        for (int jl = 0; jl < 4; ++jl)
            bh[0][jl] = *(const uint2*)(bh_base + lwo + jl * 64);

        u32 ah[2][4];
        #pragma unroll 2
        for (int hh = 0; hh < 32; ++hh) {
            const int cur = hh & 1, nxt = cur ^ 1;
            const int ks = hh >> 1, h = hh & 1;
            // prefetch next half-step's B fragments (hidden under MMAs)
            if (hh < 31) {
                int h1 = hh + 1;
                int ks1 = h1 >> 1, jb = (h1 & 1) * 4;
                u32 ob = (u32)(ks1 >> 2) * 8192 + (u32)(ks1 & 3) * 2048
                       + (u32)jb * 64 + lwo;
                #pragma unroll
                for (int jl = 0; jl < 4; ++jl)
                    bh[nxt][jl] = *(const uint2*)(bh_base + ob + jl * 64);
            }
            // A fragments once per k16-step (reused by both halves)
            if (h == 0) {
                const u32 aoff = (lane & 15) * AS + (ks * 16 + ((lane >> 4) << 3)) * 2
                               + wr * 32 * AS;
                #pragma unroll
                for (int mt = 0; mt < 2; ++mt)
                    ldm4(ah[mt], sb + OFF_AHI + mt * 16 * AS + aoff);
            }
            // 8 MMAs: 2 mt x 4 nt (acc index = h*4+jl)
            #pragma unroll
            for (int mt = 0; mt < 2; ++mt)
                #pragma unroll
                for (int jl = 0; jl < 4; ++jl)
                    mma16816(acc[mt][h * 4 + jl], ah[mt], (const u32*)&bh[cur][jl]);
        }

        // ---- GEMM boundary: h = relu(D1+b1) -> fp16 back into A ----
        if (g == 0) {
            __syncthreads();   // all warps done READING x before overwrite
            #pragma unroll
            for (int mt = 0; mt < 2; ++mt)
                #pragma unroll
                for (int j = 0; j < 8; ++j) {
                    float* a4 = acc[mt][j];
                    int r  = wr * 32 + mt * 16 + (lane >> 2);
                    int cc = wc * 64 + j * 8 + (lane & 3) * 2;
                    float bx = sb1[cc], by = sb1[cc + 1];
                    float h0 = fmaxf(a4[0] + bx, 0.f), h1 = fmaxf(a4[1] + by, 0.f);
                    float h2 = fmaxf(a4[2] + bx, 0.f), h3 = fmaxf(a4[3] + by, 0.f);
                    __half2 hiA = __floats2half2_rn(h0, h1);
                    __half2 hiB = __floats2half2_rn(h2, h3);
                    *(__half2*)(smem + OFF_AHI + r * AS + cc * 2)       = hiA;
                    *(__half2*)(smem + OFF_AHI + (r + 8) * AS + cc * 2) = hiB;
                }
            __syncthreads();   // h visible to all warps before GEMM2
            #pragma unroll
            for (int i = 0; i < 2; ++i)
                #pragma unroll
                for (int j = 0; j < 8; ++j)
                    #pragma unroll
                    for (int q = 0; q < 4; ++q) acc[i][j][q] = 0.f;
        }
    }

    // ---- final epilogue: g = h * sigmoid(D2+b2); g overlays A region ----
    float* gt = (float*)smem;   // [64][264] fp32 over A (and beyond, to 67584)
    {
        float gv[2][8][4];
        #pragma unroll
        for (int mt = 0; mt < 2; ++mt)
            #pragma unroll
            for (int j = 0; j < 8; ++j) {
                float* a4 = acc[mt][j];
                int r  = wr * 32 + mt * 16 + (lane >> 2);
                int cc = wc * 64 + j * 8 + (lane & 3) * 2;
                float bx = sb2[cc], by = sb2[cc + 1];
                float2 hA = __half22float2(*(__half2*)(smem + OFF_AHI + r * AS + cc * 2));
                float2 hB = __half22float2(*(__half2*)(smem + OFF_AHI + (r + 8) * AS + cc * 2));
                gv[mt][j][0] = hA.x / (1.f + __expf(-(a4[0] + bx)));
                gv[mt][j][1] = hA.y / (1.f + __expf(-(a4[1] + by)));
                gv[mt][j][2] = hB.x / (1.f + __expf(-(a4[2] + bx)));
                gv[mt][j][3] = hB.y / (1.f + __expf(-(a4[3] + by)));
            }
        __syncthreads();   // everyone done reading h before overwrite
        #pragma unroll
        for (int mt = 0; mt < 2; ++mt)
            #pragma unroll
            for (int j = 0; j < 8; ++j) {
                int r  = wr * 32 + mt * 16 + (lane >> 2);
                int cc = wc * 64 + j * 8 + (lane & 3) * 2;
                *(float2*)&gt[r * 264 + cc]       = make_float2(gv[mt][j][0], gv[mt][j][1]);
                *(float2*)&gt[(r + 8) * 264 + cc] = make_float2(gv[mt][j][2], gv[mt][j][3]);
            }
    }
    __syncthreads();

    // ---- segment reduction: sorted batch -> runs; one thread per column ----
    {
        const int ccol = tid;              // 256 threads = 256 columns
        int cur = bseg[0];
        float rsum = 0.f, rmax = 0.f;
        #pragma unroll 1
        for (int r = 0; r < BM; ++r) {
            int s = bseg[r];
            float g = gt[r * 264 + ccol];
            if (s != cur) {
                if (cur >= 0) {
                    atomicAdd(&out[(size_t)cur * 2 * H + H + ccol], rsum);
                    atomicMax((unsigned int*)&out[(size_t)cur * 2 * H + ccol],
                              __float_as_uint(rmax));   // g >= 0 always
                }
                cur = s; rsum = 0.f; rmax = 0.f;
            }
            if (s >= 0) { rsum += g; rmax = fmaxf(rmax, g); }
        }
        if (cur >= 0) {
            atomicAdd(&out[(size_t)cur * 2 * H + H + ccol], rsum);
            atomicMax((unsigned int*)&out[(size_t)cur * 2 * H + ccol],
                      __float_as_uint(rmax));
        }
        if (tid == 0) {                    // counts: once per run per tile
            int cur2 = bseg[0]; int cnt = 0;
            for (int r = 0; r < BM; ++r) {
                int s = bseg[r];
                if (s != cur2) {
                    if (cur2 >= 0) atomicAdd(&g_counts[cur2], cnt);
                    cur2 = s; cnt = 0;
                }
                if (s >= 0) cnt++;
            }
            if (cur2 >= 0) atomicAdd(&g_counts[cur2], cnt);
        }
    }
}

// ---------------------------------------------------------------------------
// Kernel 4: mean = sum / count (empty segments stay 0)
// ---------------------------------------------------------------------------
__global__ void finalize_kernel(float* out) {
    int i = blockIdx.x * blockDim.x + threadIdx.x;  // NSEG * H
    if (i < NSEG * H) {
        int seg = i >> 8;
        int c   = i & (H - 1);
        int cnt = g_counts[seg];
        float denom = cnt > 0 ? (float)cnt : 1.f;
        out[(size_t)seg * 2 * H + H + c] *= (1.f / denom);
    }
}

extern "C" void kernel_launch(void* const* d_in, const int* in_sizes, int n_in,
                              void* d_out, int out_size) {
    const float* x     = (const float*)d_in[0];
    const void*  batch = d_in[1];
    const float* W1    = (const float*)d_in[2];
    const float* b1    = (const float*)d_in[3];
    const float* W2    = (const float*)d_in[4];
    const float* b2    = (const float*)d_in[5];
    float* out = (float*)d_out;

    int N = in_sizes[0] / H;

    cudaFuncSetAttribute(fused_kernel,
                         cudaFuncAttributeMaxDynamicSharedMemorySize, SMEM_TOTAL);

    zero_kernel<<<(out_size + 255) / 256, 256>>>(out, out_size, batch, N);
    wprep_kernel<<<512, 256>>>(W1, W2);

    int nblk = (N + BM - 1) / BM;
    fused_kernel<<<nblk, 256, SMEM_TOTAL>>>(x, batch, b1, b2, out, N);

    finalize_kernel<<<(NSEG * H + 255) / 256, 256>>>(out);
}

// round 11
// speedup vs baseline: 1.4288x; 1.0323x over previous
#include <cuda_runtime.h>
#include <cuda_fp16.h>
#include <cstdint>
#include <math.h>

#define H 256
#define BM 64
#define NSEG 512
#define AS 528           // A row stride in bytes (264 fp16, padded)

typedef unsigned long long u64;
typedef unsigned int       u32;

// -------- device scratch (no allocations allowed) --------
__device__ int g_counts[NSEG];
__device__ int g_is64;
// W (fp16) packed in per-lane b-fragment layout:
// [gemm(2)][kchunk(4)] blocks of 8192 u32 = [ks(4)][nt(32)][lane(32)][reg(2)]
__device__ __align__(16) u32 g_Wb[65536];

// -------- SMEM layout (bytes) --------
#define OFF_AHI   0                    // [64][264] fp16 = 33792
#define OFF_BSEG  67584                // 64 ints (gtile fp32 needs 0..67583)
#define OFF_BIAS  67840                // b1[256], b2[256] fp32 = 2048
#define SMEM_TOTAL 69888
// g tile (final): fp32 [64][264] overlays bytes 0..67583 (A dead by then)

// -------- PTX helpers (legal on plain sm_103 target) --------
__device__ __forceinline__ void ldm4(u32* r, u32 addr) {
    asm volatile("ldmatrix.sync.aligned.m8n8.x4.shared.b16 {%0,%1,%2,%3},[%4];"
        : "=r"(r[0]), "=r"(r[1]), "=r"(r[2]), "=r"(r[3]) : "r"(addr));
}
__device__ __forceinline__ void mma16816(float* d, const u32* a, const u32* b) {
    asm volatile(
        "mma.sync.aligned.m16n8k16.row.col.f32.f16.f16.f32 "
        "{%0,%1,%2,%3},{%4,%5,%6,%7},{%8,%9},{%0,%1,%2,%3};"
        : "+f"(d[0]), "+f"(d[1]), "+f"(d[2]), "+f"(d[3])
        : "r"(a[0]), "r"(a[1]), "r"(a[2]), "r"(a[3]), "r"(b[0]), "r"(b[1]));
}

// ---------------------------------------------------------------------------
// Kernel 1: W prep (fp32 -> fp16, b-fragment layout) + zero out/counts +
// batch dtype detection, all fused into one launch. 512 blocks x 256 thr.
// ---------------------------------------------------------------------------
__global__ void prep_kernel(const float* __restrict__ W1,
                            const float* __restrict__ W2,
                            float* out, int out_size,
                            const void* batch, int N) {
    int id = blockIdx.x * 256 + threadIdx.x;     // 131072 total
    // zero output (262144 floats) + counts
    out[id] = 0.0f;
    out[id + 131072] = 0.0f;
    if (id < NSEG) g_counts[id] = 0;
    if (id == 0) {
        const int* bw = (const int*)batch;
        int o = ((N - 1) & 1) ? (N - 1) : (N - 2);
        int orv = 0;
        if (o >= 4) orv = bw[o] | bw[o - 2] | bw[o - 4];
        else if (o >= 0) orv = bw[o];
        g_is64 = (orv == 0) ? 1 : 0;
    }
    // W pack
    int gemm = id >> 16, rem = id & 65535;
    int n = rem >> 8, k = rem & 255;
    float w = (gemm ? W2 : W1)[n * H + k];
    __half hi = __float2half_rn(w);
    int chunk = k >> 6, ks = (k >> 4) & 3, kk = k & 15;
    int nt = n >> 3, nn = n & 7;
    int lane = nn * 4 + ((kk & 7) >> 1);
    int reg  = kk >> 3;
    int half_i = kk & 1;
    u32 base = (u32)((gemm * 4 + chunk) * 8192
                     + ((ks * 32 + nt) * 32 + lane) * 2 + reg);
    __half* wb = (__half*)g_Wb;
    wb[(size_t)base * 2 + half_i] = hi;
}

// ---------------------------------------------------------------------------
// Kernel 2: fused  relu(xW1^T+b1) -> sigmoid(hW2^T+b2) gate -> segment reduce.
// Plain fp16 HMMA. Warp grid 2x4 (rows 32*wr, cols 64*wc). Mainloop iterates
// FULL k16-steps (16 MMAs per iteration, 32 iterations) with a full-step
// B double-buffer loaded via __ldg — wide MMA window hides L2 latency.
// ---------------------------------------------------------------------------
extern "C" __global__ void __launch_bounds__(256, 2)
fused_kernel(const float* __restrict__ x, const void* __restrict__ batch,
             const float* __restrict__ b1, const float* __restrict__ b2,
             float* __restrict__ out, int N)
{
    extern __shared__ char smem[];
    const u32 sb = (u32)__cvta_generic_to_shared(smem);
    const int tid  = threadIdx.x;
    const int w    = tid >> 5;
    const int lane = tid & 31;
    const int wr   = w >> 2;            // 0..1: row group (32 rows)
    const int wc   = w & 3;             // 0..3: col group (64 cols)
    const int row0 = blockIdx.x * BM;
    float* sb1 = (float*)(smem + OFF_BIAS);
    float* sb2 = sb1 + H;
    int* bseg = (int*)(smem + OFF_BSEG);

    // ---- bias + segment ids ----
    sb1[tid] = b1[tid];
    sb2[tid] = b2[tid];
    if (tid < BM) {
        int r = row0 + tid;
        int s = -1;
        if (r < N) {
            if (g_is64) s = (int)((const long long*)batch)[r];
            else        s = ((const int*)batch)[r];
        }
        bseg[tid] = s;
    }

    // ---- load x tile fp32 -> fp16 into AHI ([64][264] padded) ----
    {
        const float4* xg = (const float4*)x;
        #pragma unroll
        for (int it = 0; it < 16; ++it) {
            int f = tid + it * 256;            // 4096 float4s
            int r = f >> 6, k4 = f & 63;
            float4 v = make_float4(0.f, 0.f, 0.f, 0.f);
            if (row0 + r < N) v = xg[(size_t)(row0 + r) * (H / 4) + k4];
            __half2 h01 = __floats2half2_rn(v.x, v.y);
            __half2 h23 = __floats2half2_rn(v.z, v.w);
            char* pa = smem + OFF_AHI + r * AS + k4 * 8;
            *(__half2*)pa = h01;  *(__half2*)(pa + 4) = h23;
        }
    }
    __syncthreads();   // x tile visible to all warps

    float acc[2][8][4];
    #pragma unroll
    for (int i = 0; i < 2; ++i)
        #pragma unroll
        for (int j = 0; j < 8; ++j)
            #pragma unroll
            for (int q = 0; q < 4; ++q) acc[i][j][q] = 0.f;

    // ---- 2 GEMMs, K=256 = 16 full k16-steps each ----
    #pragma unroll 1
    for (int g = 0; g < 2; ++g) {
        const u32* bb = g_Wb + g * 32768;                 // fp16 W blocks
        const u32 lwo = (u32)(wc * 512 + lane * 2);       // nt = wc*8 base

        uint2 bh[2][8];
        // preload step 0 (all 8 nt fragments)
        #pragma unroll
        for (int j = 0; j < 8; ++j)
            bh[0][j] = __ldg((const uint2*)(bb + lwo + j * 64));

        u32 ah[2][4];
        #pragma unroll 2
        for (int ks = 0; ks < 16; ++ks) {
            const int cur = ks & 1;
            // A fragments for this step (LDSM latency covered by MMA window)
            const u32 aoff = (lane & 15) * AS + (ks * 16 + ((lane >> 4) << 3)) * 2
                           + wr * 32 * AS;
            ldm4(ah[0], sb + OFF_AHI + aoff);
            ldm4(ah[1], sb + OFF_AHI + 16 * AS + aoff);
            // prefetch next full step's B fragments
            if (ks < 15) {
                int k1 = ks + 1;
                u32 ob = (u32)(k1 >> 2) * 8192 + (u32)(k1 & 3) * 2048 + lwo;
                #pragma unroll
                for (int j = 0; j < 8; ++j)
                    bh[cur ^ 1][j] = __ldg((const uint2*)(bb + ob + j * 64));
            }
            // 16 MMAs: 2 mt x 8 nt
            #pragma unroll
            for (int mt = 0; mt < 2; ++mt)
                #pragma unroll
                for (int j = 0; j < 8; ++j)
                    mma16816(acc[mt][j], ah[mt], (const u32*)&bh[cur][j]);
        }

        // ---- GEMM boundary: h = relu(D1+b1) -> fp16 back into A ----
        if (g == 0) {
            __syncthreads();   // all warps done READING x before overwrite
            #pragma unroll
            for (int mt = 0; mt < 2; ++mt)
                #pragma unroll
                for (int j = 0; j < 8; ++j) {
                    float* a4 = acc[mt][j];
                    int r  = wr * 32 + mt * 16 + (lane >> 2);
                    int cc = wc * 64 + j * 8 + (lane & 3) * 2;
                    float bx = sb1[cc], by = sb1[cc + 1];
                    float h0 = fmaxf(a4[0] + bx, 0.f), h1 = fmaxf(a4[1] + by, 0.f);
                    float h2 = fmaxf(a4[2] + bx, 0.f), h3 = fmaxf(a4[3] + by, 0.f);
                    __half2 hiA = __floats2half2_rn(h0, h1);
                    __half2 hiB = __floats2half2_rn(h2, h3);
                    *(__half2*)(smem + OFF_AHI + r * AS + cc * 2)       = hiA;
                    *(__half2*)(smem + OFF_AHI + (r + 8) * AS + cc * 2) = hiB;
                }
            __syncthreads();   // h visible to all warps before GEMM2
            #pragma unroll
            for (int i = 0; i < 2; ++i)
                #pragma unroll
                for (int j = 0; j < 8; ++j)
                    #pragma unroll
                    for (int q = 0; q < 4; ++q) acc[i][j][q] = 0.f;
        }
    }

    // ---- final epilogue: g = h * sigmoid(D2+b2); g overlays A region ----
    float* gt = (float*)smem;   // [64][264] fp32 over A region
    {
        float gv[2][8][4];
        #pragma unroll
        for (int mt = 0; mt < 2; ++mt)
            #pragma unroll
            for (int j = 0; j < 8; ++j) {
                float* a4 = acc[mt][j];
                int r  = wr * 32 + mt * 16 + (lane >> 2);
                int cc = wc * 64 + j * 8 + (lane & 3) * 2;
                float bx = sb2[cc], by = sb2[cc + 1];
                float2 hA = __half22float2(*(__half2*)(smem + OFF_AHI + r * AS + cc * 2));
                float2 hB = __half22float2(*(__half2*)(smem + OFF_AHI + (r + 8) * AS + cc * 2));
                gv[mt][j][0] = hA.x / (1.f + __expf(-(a4[0] + bx)));
                gv[mt][j][1] = hA.y / (1.f + __expf(-(a4[1] + by)));
                gv[mt][j][2] = hB.x / (1.f + __expf(-(a4[2] + bx)));
                gv[mt][j][3] = hB.y / (1.f + __expf(-(a4[3] + by)));
            }
        __syncthreads();   // everyone done reading h before overwrite
        #pragma unroll
        for (int mt = 0; mt < 2; ++mt)
            #pragma unroll
            for (int j = 0; j < 8; ++j) {
                int r  = wr * 32 + mt * 16 + (lane >> 2);
                int cc = wc * 64 + j * 8 + (lane & 3) * 2;
                *(float2*)&gt[r * 264 + cc]       = make_float2(gv[mt][j][0], gv[mt][j][1]);
                *(float2*)&gt[(r + 8) * 264 + cc] = make_float2(gv[mt][j][2], gv[mt][j][3]);
            }
    }
    __syncthreads();

    // ---- segment reduction: sorted batch -> runs; one thread per column ----
    {
        const int ccol = tid;              // 256 threads = 256 columns
        int cur = bseg[0];
        float rsum = 0.f, rmax = 0.f;
        #pragma unroll 1
        for (int r = 0; r < BM; ++r) {
            int s = bseg[r];
            float g = gt[r * 264 + ccol];
            if (s != cur) {
                if (cur >= 0) {
                    atomicAdd(&out[(size_t)cur * 2 * H + H + ccol], rsum);
                    atomicMax((unsigned int*)&out[(size_t)cur * 2 * H + ccol],
                              __float_as_uint(rmax));   // g >= 0 always
                }
                cur = s; rsum = 0.f; rmax = 0.f;
            }
            if (s >= 0) { rsum += g; rmax = fmaxf(rmax, g); }
        }
        if (cur >= 0) {
            atomicAdd(&out[(size_t)cur * 2 * H + H + ccol], rsum);
            atomicMax((unsigned int*)&out[(size_t)cur * 2 * H + ccol],
                      __float_as_uint(rmax));
        }
        if (tid == 0) {                    // counts: once per run per tile
            int cur2 = bseg[0]; int cnt = 0;
            for (int r = 0; r < BM; ++r) {
                int s = bseg[r];
                if (s != cur2) {
                    if (cur2 >= 0) atomicAdd(&g_counts[cur2], cnt);
                    cur2 = s; cnt = 0;
                }
                if (s >= 0) cnt++;
            }
            if (cur2 >= 0) atomicAdd(&g_counts[cur2], cnt);
        }
    }
}

// ---------------------------------------------------------------------------
// Kernel 3: mean = sum / count (empty segments stay 0)
// ---------------------------------------------------------------------------
__global__ void finalize_kernel(float* out) {
    int i = blockIdx.x * blockDim.x + threadIdx.x;  // NSEG * H
    if (i < NSEG * H) {
        int seg = i >> 8;
        int c   = i & (H - 1);
        int cnt = g_counts[seg];
        float denom = cnt > 0 ? (float)cnt : 1.f;
        out[(size_t)seg * 2 * H + H + c] *= (1.f / denom);
    }
}

extern "C" void kernel_launch(void* const* d_in, const int* in_sizes, int n_in,
                              void* d_out, int out_size) {
    const float* x     = (const float*)d_in[0];
    const void*  batch = d_in[1];
    const float* W1    = (const float*)d_in[2];
    const float* b1    = (const float*)d_in[3];
    const float* W2    = (const float*)d_in[4];
    const float* b2    = (const float*)d_in[5];
    float* out = (float*)d_out;

    int N = in_sizes[0] / H;

    cudaFuncSetAttribute(fused_kernel,
                         cudaFuncAttributeMaxDynamicSharedMemorySize, SMEM_TOTAL);

    prep_kernel<<<512, 256>>>(W1, W2, out, out_size, batch, N);

    int nblk = (N + BM - 1) / BM;
    fused_kernel<<<nblk, 256, SMEM_TOTAL>>>(x, batch, b1, b2, out, N);

    finalize_kernel<<<(NSEG * H + 255) / 256, 256>>>(out);
}